// round 3
// baseline (speedup 1.0000x reference)
#include <cuda_runtime.h>
#include <cuda_bf16.h>
#include <math.h>

// Problem constants
#define SQ   1024
#define DIM  7168
#define NH   128
#define DNOPE 128
#define DROPE 64
#define DVAL 128
#define DQH  192         // DNOPE + DROPE
#define RQ   1536
#define RKV  512
#define HDQ  (NH*DQH)            // 24576
#define HKV  (NH*(DNOPE+DVAL))   // 32768
#define HDV  (NH*DVAL)           // 16384
#define EPS  1e-6f

// Scratch (device globals: allocation-free per harness rules)
__device__ float g_qa [SQ*RQ];
__device__ float g_qan[SQ*RQ];
__device__ float g_q  [SQ*HDQ];
__device__ float g_ckv[SQ*(RKV+DROPE)];
__device__ float g_kvn[SQ*RKV];
__device__ float g_kv [SQ*HKV];
__device__ float g_kpe[SQ*DROPE];
__device__ float g_ao [SQ*HDV];

// ---------------------------------------------------------------------------
// Generic NT SGEMM: C[M,N] = A[M,K] * B[N,K]^T, all row-major, K contiguous.
// Tiles: BM=128, BN=64, BK=16; 256 threads; 8x4 microtile per thread.
// Requires M%128==0, N%64==0, K%16==0 (true for all calls here).
// ---------------------------------------------------------------------------
__global__ void __launch_bounds__(256) gemm_nt_kernel(
    const float* __restrict__ A, const float* __restrict__ B,
    float* __restrict__ C, int M, int N, int K) {
  __shared__ float As[16][128];
  __shared__ float Bs[16][64];
  const int bm = blockIdx.y * 128;
  const int bn = blockIdx.x * 64;
  const int tid = threadIdx.x;
  const int ty = tid >> 4;          // 0..15 -> row group
  const int tx = tid & 15;          // 0..15 -> col group
  const int lr = tid >> 2;          // 0..63 load row
  const int lc = (tid & 3) << 2;    // 0,4,8,12 load col (float4)

  const float* Ap0 = A + (size_t)(bm + lr)      * K + lc;
  const float* Ap1 = A + (size_t)(bm + lr + 64) * K + lc;
  const float* Bp  = B + (size_t)(bn + lr)      * K + lc;

  float acc[8][4];
#pragma unroll
  for (int i = 0; i < 8; i++)
#pragma unroll
    for (int j = 0; j < 4; j++) acc[i][j] = 0.f;

  for (int k0 = 0; k0 < K; k0 += 16) {
    float4 a0 = *(const float4*)(Ap0 + k0);
    float4 a1 = *(const float4*)(Ap1 + k0);
    float4 b0 = *(const float4*)(Bp  + k0);
    __syncthreads();
    As[lc+0][lr]    = a0.x; As[lc+1][lr]    = a0.y; As[lc+2][lr]    = a0.z; As[lc+3][lr]    = a0.w;
    As[lc+0][lr+64] = a1.x; As[lc+1][lr+64] = a1.y; As[lc+2][lr+64] = a1.z; As[lc+3][lr+64] = a1.w;
    Bs[lc+0][lr]    = b0.x; Bs[lc+1][lr]    = b0.y; Bs[lc+2][lr]    = b0.z; Bs[lc+3][lr]    = b0.w;
    __syncthreads();
#pragma unroll
    for (int k = 0; k < 16; k++) {
      float4 ra0 = *(const float4*)&As[k][ty*8];
      float4 ra1 = *(const float4*)&As[k][ty*8+4];
      float4 rb4 = *(const float4*)&Bs[k][tx*4];
      float ra[8] = {ra0.x,ra0.y,ra0.z,ra0.w,ra1.x,ra1.y,ra1.z,ra1.w};
      float rb[4] = {rb4.x,rb4.y,rb4.z,rb4.w};
#pragma unroll
      for (int i = 0; i < 8; i++)
#pragma unroll
        for (int j = 0; j < 4; j++)
          acc[i][j] += ra[i]*rb[j];
    }
  }
#pragma unroll
  for (int i = 0; i < 8; i++) {
    float* Cp = C + (size_t)(bm + ty*8 + i)*N + bn + tx*4;
    *(float4*)Cp = make_float4(acc[i][0], acc[i][1], acc[i][2], acc[i][3]);
  }
}

// ---------------------------------------------------------------------------
// RMSNorm: out[row, 0..n) = x * rsqrt(mean(x^2)+eps) * w, one block per row.
// ---------------------------------------------------------------------------
__global__ void __launch_bounds__(256) rmsnorm_kernel(
    const float* __restrict__ in, const float* __restrict__ w,
    float* __restrict__ out, int n, int istride, int ostride) {
  const int row = blockIdx.x;
  const float* x = in + (size_t)row * istride;
  float s = 0.f;
  for (int i = threadIdx.x; i < n; i += 256) { float v = x[i]; s += v*v; }
  __shared__ float red[256];
  red[threadIdx.x] = s;
  __syncthreads();
  for (int off = 128; off > 0; off >>= 1) {
    if (threadIdx.x < off) red[threadIdx.x] += red[threadIdx.x + off];
    __syncthreads();
  }
  const float inv = rsqrtf(red[0] / (float)n + EPS);
  float* o = out + (size_t)row * ostride;
  for (int i = threadIdx.x; i < n; i += 256) o[i] = x[i] * inv * w[i];
}

// ---------------------------------------------------------------------------
// RoPE on q_pe (in-place in g_q). One thread per (s, h, d<32) rotation pair.
// ---------------------------------------------------------------------------
__global__ void rope_q_kernel(float* __restrict__ q,
                              const float* __restrict__ cosb,
                              const float* __restrict__ sinb) {
  int idx = blockIdx.x * blockDim.x + threadIdx.x;   // SQ*NH*32
  int d = idx & 31;
  int h = (idx >> 5) & (NH - 1);
  int s = idx >> 12;
  float* base = q + (size_t)s * HDQ + h * DQH + DNOPE;
  float x1 = base[d], x2 = base[d + 32];
  float c1 = cosb[s*DROPE + d],      s1 = sinb[s*DROPE + d];
  float c2 = cosb[s*DROPE + d + 32], s2 = sinb[s*DROPE + d + 32];
  base[d]      = x1*c1 - x2*s1;
  base[d + 32] = x2*c2 + x1*s2;
}

// RoPE on k_pe (from ckv tail cols) -> g_kpe[S, 64]
__global__ void rope_k_kernel(const float* __restrict__ ckv,
                              const float* __restrict__ cosb,
                              const float* __restrict__ sinb,
                              float* __restrict__ kpe) {
  int idx = blockIdx.x * blockDim.x + threadIdx.x;  // SQ*32
  int d = idx & 31;
  int s = idx >> 5;
  float x1 = ckv[(size_t)s*(RKV+DROPE) + RKV + d];
  float x2 = ckv[(size_t)s*(RKV+DROPE) + RKV + 32 + d];
  float c1 = cosb[s*DROPE + d],      s1 = sinb[s*DROPE + d];
  float c2 = cosb[s*DROPE + d + 32], s2 = sinb[s*DROPE + d + 32];
  kpe[s*DROPE + d]      = x1*c1 - x2*s1;
  kpe[s*DROPE + 32 + d] = x2*c2 + x1*s2;
}

// ---------------------------------------------------------------------------
// Flash attention (causal), one block per (head, 64-row q tile), 256 threads.
// Thread (r = tid/4, g = tid%4) computes scores for cols g*16..g*16+15 and
// owns output columns {g + 4*c : c in 0..31} (bank-conflict-free V reads).
// ---------------------------------------------------------------------------
#define QK_STR 193
#define PS_STR 65
#define FLASH_SMEM ((2*64*QK_STR + 64*128 + 64*PS_STR) * 4)

__global__ void __launch_bounds__(256) flash_kernel(
    const float* __restrict__ q, const float* __restrict__ kv,
    const float* __restrict__ kpe, float* __restrict__ ao) {
  extern __shared__ float sm[];
  float* Qs = sm;                      // 64 x QK_STR
  float* Ks = Qs + 64*QK_STR;          // 64 x QK_STR
  float* Vs = Ks + 64*QK_STR;          // 64 x 128
  float* Ps = Vs + 64*128;             // 64 x PS_STR

  const int h  = blockIdx.x;
  const int q0 = blockIdx.y * 64;
  const int tid = threadIdx.x;
  const int r = tid >> 2;
  const int g = tid & 3;

  // load Q tile (nope + already-roped pe, contiguous in g_q)
  for (int idx = tid; idx < 64*DQH; idx += 256) {
    int row = idx / DQH, d = idx % DQH;
    Qs[row*QK_STR + d] = q[(size_t)(q0+row)*HDQ + h*DQH + d];
  }

  float m = -INFINITY, l = 0.f;
  float o[32];
#pragma unroll
  for (int c = 0; c < 32; c++) o[c] = 0.f;
  const float scale = rsqrtf((float)DQH);

  const int nkt = blockIdx.y + 1;
  for (int kt = 0; kt < nkt; kt++) {
    const int k0 = kt * 64;
    __syncthreads();
    for (int idx = tid; idx < 64*DQH; idx += 256) {
      int row = idx / DQH, d = idx % DQH;
      Ks[row*QK_STR + d] = (d < DNOPE)
          ? kv[(size_t)(k0+row)*HKV + h*(DNOPE+DVAL) + d]
          : kpe[(k0+row)*DROPE + (d - DNOPE)];
    }
    for (int idx = tid; idx < 64*128; idx += 256) {
      int row = idx >> 7, d = idx & 127;
      Vs[idx] = kv[(size_t)(k0+row)*HKV + h*(DNOPE+DVAL) + DNOPE + d];
    }
    __syncthreads();

    // scores: sc[j] = Q[r] . K[g*16+j]
    float sc[16];
#pragma unroll
    for (int j = 0; j < 16; j++) sc[j] = 0.f;
    const float* qr = Qs + r*QK_STR;
    for (int d0 = 0; d0 < DQH; d0 += 8) {
      float qd[8];
#pragma unroll
      for (int dd = 0; dd < 8; dd++) qd[dd] = qr[d0+dd];
#pragma unroll
      for (int j = 0; j < 16; j++) {
        const float* kr = Ks + (g*16+j)*QK_STR + d0;
#pragma unroll
        for (int dd = 0; dd < 8; dd++) sc[j] += qd[dd]*kr[dd];
      }
    }
#pragma unroll
    for (int j = 0; j < 16; j++) {
      int c = g*16 + j;
      sc[j] = (k0 + c <= q0 + r) ? sc[j]*scale : -INFINITY;
    }

    // online softmax (4 threads per row share via shuffle; g = lane&3)
    float mloc = -INFINITY;
#pragma unroll
    for (int j = 0; j < 16; j++) mloc = fmaxf(mloc, sc[j]);
    mloc = fmaxf(mloc, __shfl_xor_sync(0xffffffffu, mloc, 1));
    mloc = fmaxf(mloc, __shfl_xor_sync(0xffffffffu, mloc, 2));
    float mnew = fmaxf(m, mloc);
    float alpha = expf(m - mnew);
    float lloc = 0.f;
#pragma unroll
    for (int j = 0; j < 16; j++) {
      float p = expf(sc[j] - mnew);
      lloc += p;
      Ps[r*PS_STR + g*16 + j] = p;
    }
    lloc += __shfl_xor_sync(0xffffffffu, lloc, 1);
    lloc += __shfl_xor_sync(0xffffffffu, lloc, 2);
    l = l * alpha + lloc;
    m = mnew;
#pragma unroll
    for (int c = 0; c < 32; c++) o[c] *= alpha;

    __syncwarp();
    const float* psr = Ps + r*PS_STR;
    for (int j = 0; j < 64; j++) {
      float pj = psr[j];
      const float* vr = Vs + j*128 + g;
#pragma unroll
      for (int c = 0; c < 32; c++) o[c] += pj * vr[4*c];
    }
  }

  const float invl = 1.f / l;
#pragma unroll
  for (int c = 0; c < 32; c++)
    ao[(size_t)(q0+r)*HDV + h*DVAL + g + 4*c] = o[c] * invl;
}

// ---------------------------------------------------------------------------
extern "C" void kernel_launch(void* const* d_in, const int* in_sizes, int n_in,
                              void* d_out, int out_size) {
  const float* hidden  = (const float*)d_in[0];
  const float* cosb    = (const float*)d_in[1];
  const float* sinb    = (const float*)d_in[2];
  const float* wq_a    = (const float*)d_in[3];
  const float* q_ln_w  = (const float*)d_in[4];
  const float* wq_b    = (const float*)d_in[5];
  const float* wkv_a   = (const float*)d_in[6];
  const float* kv_ln_w = (const float*)d_in[7];
  const float* wkv_b   = (const float*)d_in[8];
  const float* wo      = (const float*)d_in[9];
  float* out = (float*)d_out;

  float *qa, *qan, *q, *ckv, *kvn, *kv, *kpe, *ao;
  cudaGetSymbolAddress((void**)&qa,  g_qa);
  cudaGetSymbolAddress((void**)&qan, g_qan);
  cudaGetSymbolAddress((void**)&q,   g_q);
  cudaGetSymbolAddress((void**)&ckv, g_ckv);
  cudaGetSymbolAddress((void**)&kvn, g_kvn);
  cudaGetSymbolAddress((void**)&kv,  g_kv);
  cudaGetSymbolAddress((void**)&kpe, g_kpe);
  cudaGetSymbolAddress((void**)&ao,  g_ao);

  // q path: q_a = h @ wq_a^T ; rmsnorm ; q = qan @ wq_b^T
  gemm_nt_kernel<<<dim3(RQ/64, SQ/128), 256>>>(hidden, wq_a, qa, SQ, RQ, DIM);
  rmsnorm_kernel<<<SQ, 256>>>(qa, q_ln_w, qan, RQ, RQ, RQ);
  gemm_nt_kernel<<<dim3(HDQ/64, SQ/128), 256>>>(qan, wq_b, q, SQ, HDQ, RQ);

  // kv path: ckv = h @ wkv_a^T ; rmsnorm(first 512) ; kv = kvn @ wkv_b^T
  gemm_nt_kernel<<<dim3((RKV+DROPE)/64, SQ/128), 256>>>(hidden, wkv_a, ckv, SQ, RKV+DROPE, DIM);
  rmsnorm_kernel<<<SQ, 256>>>(ckv, kv_ln_w, kvn, RKV, RKV+DROPE, RKV);
  gemm_nt_kernel<<<dim3(HKV/64, SQ/128), 256>>>(kvn, wkv_b, kv, SQ, HKV, RKV);

  // RoPE
  rope_q_kernel<<<(SQ*NH*32)/256, 256>>>(q, cosb, sinb);
  rope_k_kernel<<<(SQ*32)/256, 256>>>(ckv, cosb, sinb, kpe);

  // causal flash attention
  cudaFuncSetAttribute(flash_kernel, cudaFuncAttributeMaxDynamicSharedMemorySize, FLASH_SMEM);
  flash_kernel<<<dim3(NH, SQ/64), 256, FLASH_SMEM>>>(q, kv, kpe, ao);

  // output projection
  gemm_nt_kernel<<<dim3(DIM/64, SQ/128), 256>>>(ao, wo, out, SQ, DIM, HDV);
}

// round 5
// speedup vs baseline: 1.4750x; 1.4750x over previous
#include <cuda_runtime.h>
#include <cuda_bf16.h>
#include <math.h>

// Problem constants
#define SQ   1024
#define DIM  7168
#define NH   128
#define DNOPE 128
#define DROPE 64
#define DVAL 128
#define DQH  192         // DNOPE + DROPE
#define RQ   1536
#define RKV  512
#define HDQ  (NH*DQH)            // 24576
#define HKV  (NH*(DNOPE+DVAL))   // 32768
#define HDV  (NH*DVAL)           // 16384
#define EPS  1e-6f

// Scratch (device globals: allocation-free per harness rules)
__device__ float g_qa [SQ*RQ];
__device__ float g_qan[SQ*RQ];
__device__ float g_q  [SQ*HDQ];
__device__ float g_ckv[SQ*(RKV+DROPE)];
__device__ float g_kvn[SQ*RKV];
__device__ float g_kv [SQ*HKV];
__device__ float g_kpe[SQ*DROPE];
__device__ float g_ao [SQ*HDV];

// ---------------------------------------------------------------------------
// TF32 tensor-core NT GEMM: C[M,N] = A[M,K] * B[N,K]^T (row-major, K contig).
// CTA tile 128x128x16, 256 threads (8 warps), warp tile 64x32 via
// mma.sync.m16n8k8 tf32. fp32->tf32 (cvt.rna) at smem staging.
// Requires M%128==0, K%16==0, N even. N tail handled by guards.
// Grid: x = M/128 (fast dim -> concurrent CTAs share B tiles in L2).
// ---------------------------------------------------------------------------
#define SSTR 20   // smem row stride (16 + 4 pad): conflict-free fragment LDS

__device__ __forceinline__ unsigned f2tf(float f) {
  unsigned u;
  asm("cvt.rna.tf32.f32 %0, %1;" : "=r"(u) : "f"(f));
  return u;
}

__device__ __forceinline__ void mma_tf32(float* d, const unsigned* a, const unsigned* b) {
  asm volatile(
    "mma.sync.aligned.m16n8k8.row.col.f32.tf32.tf32.f32 "
    "{%0,%1,%2,%3},{%4,%5,%6,%7},{%8,%9},{%0,%1,%2,%3};"
    : "+f"(d[0]), "+f"(d[1]), "+f"(d[2]), "+f"(d[3])
    : "r"(a[0]), "r"(a[1]), "r"(a[2]), "r"(a[3]), "r"(b[0]), "r"(b[1]));
}

__global__ void __launch_bounds__(256, 1) gemm_tf32_nt(
    const float* __restrict__ A, const float* __restrict__ B,
    float* __restrict__ C, int M, int N, int K) {
  __shared__ unsigned sA[2][128*SSTR];
  __shared__ unsigned sB[2][128*SSTR];

  const int bm  = blockIdx.x * 128;
  const int bn  = blockIdx.y * 128;
  const int tid = threadIdx.x;
  const int lane = tid & 31;
  const int w    = tid >> 5;
  const int wm   = (w & 1) * 64;    // warp M offset: 0 / 64
  const int wn   = (w >> 1) * 32;   // warp N offset: 0 / 32 / 64 / 96
  const int g    = lane >> 2;       // 0..7
  const int tig  = lane & 3;        // 0..3

  // staging: each thread loads 2 float4 of A and 2 float4 of B per stage
  const int lr0 = tid >> 2;         // rows 0..63  (j=0)
  const int lr1 = lr0 + 64;         // rows 64..127 (j=1)
  const int lc4 = (tid & 3) * 4;    // k offset 0/4/8/12

  const float* Ap0 = A + (size_t)(bm + lr0) * K + lc4;
  const float* Ap1 = A + (size_t)(bm + lr1) * K + lc4;
  const bool bok0 = (bn + lr0) < N;
  const bool bok1 = (bn + lr1) < N;
  const float* Bp0 = B + (size_t)(bn + (bok0 ? lr0 : 0)) * K + lc4;
  const float* Bp1 = B + (size_t)(bn + (bok1 ? lr1 : 0)) * K + lc4;

  const int soff0 = lr0 * SSTR + lc4;
  const int soff1 = lr1 * SSTR + lc4;

  float acc[4][4][4];
#pragma unroll
  for (int mt = 0; mt < 4; mt++)
#pragma unroll
    for (int nt = 0; nt < 4; nt++)
#pragma unroll
      for (int i = 0; i < 4; i++) acc[mt][nt][i] = 0.f;

  float4 va0, va1, vb0, vb1;

  // prologue: stage 0
  va0 = *(const float4*)(Ap0);
  va1 = *(const float4*)(Ap1);
  vb0 = bok0 ? *(const float4*)(Bp0) : make_float4(0,0,0,0);
  vb1 = bok1 ? *(const float4*)(Bp1) : make_float4(0,0,0,0);
  {
    unsigned* a0 = &sA[0][soff0]; unsigned* a1 = &sA[0][soff1];
    unsigned* b0 = &sB[0][soff0]; unsigned* b1 = &sB[0][soff1];
    a0[0]=f2tf(va0.x); a0[1]=f2tf(va0.y); a0[2]=f2tf(va0.z); a0[3]=f2tf(va0.w);
    a1[0]=f2tf(va1.x); a1[1]=f2tf(va1.y); a1[2]=f2tf(va1.z); a1[3]=f2tf(va1.w);
    b0[0]=f2tf(vb0.x); b0[1]=f2tf(vb0.y); b0[2]=f2tf(vb0.z); b0[3]=f2tf(vb0.w);
    b1[0]=f2tf(vb1.x); b1[1]=f2tf(vb1.y); b1[2]=f2tf(vb1.z); b1[3]=f2tf(vb1.w);
  }
  __syncthreads();

  int p = 0;
  for (int k0 = 16; k0 <= K; k0 += 16) {
    const bool more = (k0 < K);
    if (more) {
      va0 = *(const float4*)(Ap0 + k0);
      va1 = *(const float4*)(Ap1 + k0);
      vb0 = bok0 ? *(const float4*)(Bp0 + k0) : make_float4(0,0,0,0);
      vb1 = bok1 ? *(const float4*)(Bp1 + k0) : make_float4(0,0,0,0);
    }

    // compute stage p
#pragma unroll
    for (int ks = 0; ks < 2; ks++) {
      const int kb = ks * 8;
      unsigned af[4][4], bf[4][2];
#pragma unroll
      for (int mt = 0; mt < 4; mt++) {
        const int row = wm + mt*16 + g;
        af[mt][0] = sA[p][ row      *SSTR + kb + tig    ];
        af[mt][1] = sA[p][(row + 8) *SSTR + kb + tig    ];
        af[mt][2] = sA[p][ row      *SSTR + kb + tig + 4];
        af[mt][3] = sA[p][(row + 8) *SSTR + kb + tig + 4];
      }
#pragma unroll
      for (int nt = 0; nt < 4; nt++) {
        const int col = wn + nt*8 + g;
        bf[nt][0] = sB[p][col*SSTR + kb + tig    ];
        bf[nt][1] = sB[p][col*SSTR + kb + tig + 4];
      }
#pragma unroll
      for (int mt = 0; mt < 4; mt++)
#pragma unroll
        for (int nt = 0; nt < 4; nt++)
          mma_tf32(acc[mt][nt], af[mt], bf[nt]);
    }

    if (more) {
      const int q = p ^ 1;
      unsigned* a0 = &sA[q][soff0]; unsigned* a1 = &sA[q][soff1];
      unsigned* b0 = &sB[q][soff0]; unsigned* b1 = &sB[q][soff1];
      a0[0]=f2tf(va0.x); a0[1]=f2tf(va0.y); a0[2]=f2tf(va0.z); a0[3]=f2tf(va0.w);
      a1[0]=f2tf(va1.x); a1[1]=f2tf(va1.y); a1[2]=f2tf(va1.z); a1[3]=f2tf(va1.w);
      b0[0]=f2tf(vb0.x); b0[1]=f2tf(vb0.y); b0[2]=f2tf(vb0.z); b0[3]=f2tf(vb0.w);
      b1[0]=f2tf(vb1.x); b1[1]=f2tf(vb1.y); b1[2]=f2tf(vb1.z); b1[3]=f2tf(vb1.w);
    }
    __syncthreads();
    p ^= 1;
  }

  // epilogue
#pragma unroll
  for (int mt = 0; mt < 4; mt++) {
    const int row = bm + wm + mt*16 + g;
#pragma unroll
    for (int nt = 0; nt < 4; nt++) {
      const int col = bn + wn + nt*8 + 2*tig;
      if (col < N) {
        *(float2*)(C + (size_t)row*N + col)       = make_float2(acc[mt][nt][0], acc[mt][nt][1]);
        *(float2*)(C + (size_t)(row + 8)*N + col) = make_float2(acc[mt][nt][2], acc[mt][nt][3]);
      }
    }
  }
}

// ---------------------------------------------------------------------------
// RMSNorm: out[row, 0..n) = x * rsqrt(mean(x^2)+eps) * w, one block per row.
// ---------------------------------------------------------------------------
__global__ void __launch_bounds__(256) rmsnorm_kernel(
    const float* __restrict__ in, const float* __restrict__ w,
    float* __restrict__ out, int n, int istride, int ostride) {
  const int row = blockIdx.x;
  const float* x = in + (size_t)row * istride;
  float s = 0.f;
  for (int i = threadIdx.x; i < n; i += 256) { float v = x[i]; s += v*v; }
  __shared__ float red[256];
  red[threadIdx.x] = s;
  __syncthreads();
  for (int off = 128; off > 0; off >>= 1) {
    if (threadIdx.x < off) red[threadIdx.x] += red[threadIdx.x + off];
    __syncthreads();
  }
  const float inv = rsqrtf(red[0] / (float)n + EPS);
  float* o = out + (size_t)row * ostride;
  for (int i = threadIdx.x; i < n; i += 256) o[i] = x[i] * inv * w[i];
}

// ---------------------------------------------------------------------------
// RoPE on q_pe (in-place in g_q). One thread per (s, h, d<32) rotation pair.
// ---------------------------------------------------------------------------
__global__ void rope_q_kernel(float* __restrict__ q,
                              const float* __restrict__ cosb,
                              const float* __restrict__ sinb) {
  int idx = blockIdx.x * blockDim.x + threadIdx.x;   // SQ*NH*32
  int d = idx & 31;
  int h = (idx >> 5) & (NH - 1);
  int s = idx >> 12;
  float* base = q + (size_t)s * HDQ + h * DQH + DNOPE;
  float x1 = base[d], x2 = base[d + 32];
  float c1 = cosb[s*DROPE + d],      s1 = sinb[s*DROPE + d];
  float c2 = cosb[s*DROPE + d + 32], s2 = sinb[s*DROPE + d + 32];
  base[d]      = x1*c1 - x2*s1;
  base[d + 32] = x2*c2 + x1*s2;
}

// RoPE on k_pe (from ckv tail cols) -> g_kpe[S, 64]
__global__ void rope_k_kernel(const float* __restrict__ ckv,
                              const float* __restrict__ cosb,
                              const float* __restrict__ sinb,
                              float* __restrict__ kpe) {
  int idx = blockIdx.x * blockDim.x + threadIdx.x;  // SQ*32
  int d = idx & 31;
  int s = idx >> 5;
  float x1 = ckv[(size_t)s*(RKV+DROPE) + RKV + d];
  float x2 = ckv[(size_t)s*(RKV+DROPE) + RKV + 32 + d];
  float c1 = cosb[s*DROPE + d],      s1 = sinb[s*DROPE + d];
  float c2 = cosb[s*DROPE + d + 32], s2 = sinb[s*DROPE + d + 32];
  kpe[s*DROPE + d]      = x1*c1 - x2*s1;
  kpe[s*DROPE + 32 + d] = x2*c2 + x1*s2;
}

// ---------------------------------------------------------------------------
// Flash attention (causal), one block per (head, 64-row q tile), 256 threads.
// ---------------------------------------------------------------------------
#define QK_STR 193
#define PS_STR 65
#define FLASH_SMEM ((2*64*QK_STR + 64*128 + 64*PS_STR) * 4)

__global__ void __launch_bounds__(256) flash_kernel(
    const float* __restrict__ q, const float* __restrict__ kv,
    const float* __restrict__ kpe, float* __restrict__ ao) {
  extern __shared__ float sm[];
  float* Qs = sm;                      // 64 x QK_STR
  float* Ks = Qs + 64*QK_STR;          // 64 x QK_STR
  float* Vs = Ks + 64*QK_STR;          // 64 x 128
  float* Ps = Vs + 64*128;             // 64 x PS_STR

  const int h  = blockIdx.x;
  const int q0 = blockIdx.y * 64;
  const int tid = threadIdx.x;
  const int r = tid >> 2;
  const int g = tid & 3;

  for (int idx = tid; idx < 64*DQH; idx += 256) {
    int row = idx / DQH, d = idx % DQH;
    Qs[row*QK_STR + d] = q[(size_t)(q0+row)*HDQ + h*DQH + d];
  }

  float m = -INFINITY, l = 0.f;
  float o[32];
#pragma unroll
  for (int c = 0; c < 32; c++) o[c] = 0.f;
  const float scale = rsqrtf((float)DQH);

  const int nkt = blockIdx.y + 1;
  for (int kt = 0; kt < nkt; kt++) {
    const int k0 = kt * 64;
    __syncthreads();
    for (int idx = tid; idx < 64*DQH; idx += 256) {
      int row = idx / DQH, d = idx % DQH;
      Ks[row*QK_STR + d] = (d < DNOPE)
          ? kv[(size_t)(k0+row)*HKV + h*(DNOPE+DVAL) + d]
          : kpe[(k0+row)*DROPE + (d - DNOPE)];
    }
    for (int idx = tid; idx < 64*128; idx += 256) {
      int row = idx >> 7, d = idx & 127;
      Vs[idx] = kv[(size_t)(k0+row)*HKV + h*(DNOPE+DVAL) + DNOPE + d];
    }
    __syncthreads();

    float sc[16];
#pragma unroll
    for (int j = 0; j < 16; j++) sc[j] = 0.f;
    const float* qr = Qs + r*QK_STR;
    for (int d0 = 0; d0 < DQH; d0 += 8) {
      float qd[8];
#pragma unroll
      for (int dd = 0; dd < 8; dd++) qd[dd] = qr[d0+dd];
#pragma unroll
      for (int j = 0; j < 16; j++) {
        const float* kr = Ks + (g*16+j)*QK_STR + d0;
#pragma unroll
        for (int dd = 0; dd < 8; dd++) sc[j] += qd[dd]*kr[dd];
      }
    }
#pragma unroll
    for (int j = 0; j < 16; j++) {
      int c = g*16 + j;
      sc[j] = (k0 + c <= q0 + r) ? sc[j]*scale : -INFINITY;
    }

    float mloc = -INFINITY;
#pragma unroll
    for (int j = 0; j < 16; j++) mloc = fmaxf(mloc, sc[j]);
    mloc = fmaxf(mloc, __shfl_xor_sync(0xffffffffu, mloc, 1));
    mloc = fmaxf(mloc, __shfl_xor_sync(0xffffffffu, mloc, 2));
    float mnew = fmaxf(m, mloc);
    float alpha = expf(m - mnew);
    float lloc = 0.f;
#pragma unroll
    for (int j = 0; j < 16; j++) {
      float p = expf(sc[j] - mnew);
      lloc += p;
      Ps[r*PS_STR + g*16 + j] = p;
    }
    lloc += __shfl_xor_sync(0xffffffffu, lloc, 1);
    lloc += __shfl_xor_sync(0xffffffffu, lloc, 2);
    l = l * alpha + lloc;
    m = mnew;
#pragma unroll
    for (int c = 0; c < 32; c++) o[c] *= alpha;

    __syncwarp();
    const float* psr = Ps + r*PS_STR;
    for (int j = 0; j < 64; j++) {
      float pj = psr[j];
      const float* vr = Vs + j*128 + g;
#pragma unroll
      for (int c = 0; c < 32; c++) o[c] += pj * vr[4*c];
    }
  }

  const float invl = 1.f / l;
#pragma unroll
  for (int c = 0; c < 32; c++)
    ao[(size_t)(q0+r)*HDV + h*DVAL + g + 4*c] = o[c] * invl;
}

// ---------------------------------------------------------------------------
extern "C" void kernel_launch(void* const* d_in, const int* in_sizes, int n_in,
                              void* d_out, int out_size) {
  const float* hidden  = (const float*)d_in[0];
  const float* cosb    = (const float*)d_in[1];
  const float* sinb    = (const float*)d_in[2];
  const float* wq_a    = (const float*)d_in[3];
  const float* q_ln_w  = (const float*)d_in[4];
  const float* wq_b    = (const float*)d_in[5];
  const float* wkv_a   = (const float*)d_in[6];
  const float* kv_ln_w = (const float*)d_in[7];
  const float* wkv_b   = (const float*)d_in[8];
  const float* wo      = (const float*)d_in[9];
  float* out = (float*)d_out;

  float *qa, *qan, *q, *ckv, *kvn, *kv, *kpe, *ao;
  cudaGetSymbolAddress((void**)&qa,  g_qa);
  cudaGetSymbolAddress((void**)&qan, g_qan);
  cudaGetSymbolAddress((void**)&q,   g_q);
  cudaGetSymbolAddress((void**)&ckv, g_ckv);
  cudaGetSymbolAddress((void**)&kvn, g_kvn);
  cudaGetSymbolAddress((void**)&kv,  g_kv);
  cudaGetSymbolAddress((void**)&kpe, g_kpe);
  cudaGetSymbolAddress((void**)&ao,  g_ao);

  // q path: q_a = h @ wq_a^T ; rmsnorm ; q = qan @ wq_b^T
  gemm_tf32_nt<<<dim3(SQ/128, RQ/128), 256>>>(hidden, wq_a, qa, SQ, RQ, DIM);
  rmsnorm_kernel<<<SQ, 256>>>(qa, q_ln_w, qan, RQ, RQ, RQ);
  gemm_tf32_nt<<<dim3(SQ/128, HDQ/128), 256>>>(qan, wq_b, q, SQ, HDQ, RQ);

  // kv path: ckv = h @ wkv_a^T ; rmsnorm(first 512) ; kv = kvn @ wkv_b^T
  gemm_tf32_nt<<<dim3(SQ/128, (RKV+DROPE+127)/128), 256>>>(hidden, wkv_a, ckv, SQ, RKV+DROPE, DIM);
  rmsnorm_kernel<<<SQ, 256>>>(ckv, kv_ln_w, kvn, RKV, RKV+DROPE, RKV);
  gemm_tf32_nt<<<dim3(SQ/128, HKV/128), 256>>>(kvn, wkv_b, kv, SQ, HKV, RKV);

  // RoPE
  rope_q_kernel<<<(SQ*NH*32)/256, 256>>>(q, cosb, sinb);
  rope_k_kernel<<<(SQ*32)/256, 256>>>(ckv, cosb, sinb, kpe);

  // causal flash attention
  cudaFuncSetAttribute(flash_kernel, cudaFuncAttributeMaxDynamicSharedMemorySize, FLASH_SMEM);
  flash_kernel<<<dim3(NH, SQ/64), 256, FLASH_SMEM>>>(q, kv, kpe, ao);

  // output projection
  gemm_tf32_nt<<<dim3(SQ/128, DIM/128), 256>>>(ao, wo, out, SQ, DIM, HDV);
}

// round 6
// speedup vs baseline: 1.8060x; 1.2244x over previous
#include <cuda_runtime.h>
#include <cuda_bf16.h>
#include <math.h>

// Problem constants
#define SQ   1024
#define DIM  7168
#define NH   128
#define DNOPE 128
#define DROPE 64
#define DVAL 128
#define DQH  192         // DNOPE + DROPE
#define RQ   1536
#define RKV  512
#define HDQ  (NH*DQH)            // 24576
#define HKV  (NH*(DNOPE+DVAL))   // 32768
#define HDV  (NH*DVAL)           // 16384
#define EPS  1e-6f
#define NCAT 2176                // RQ + RKV + DROPE = 2112, padded to 17*128

// Scratch (device globals: allocation-free per harness rules; zero-init -> pads stay 0)
__device__ float g_hid  [SQ*DIM];
__device__ float g_wqkva[NCAT*DIM];
__device__ float g_qkva [SQ*NCAT];
__device__ float g_qan  [SQ*RQ];
__device__ float g_wqb  [HDQ*RQ];
__device__ float g_q    [SQ*HDQ];
__device__ float g_kvn  [SQ*RKV];
__device__ float g_wkvb [HKV*RKV];
__device__ float g_kv   [SQ*HKV];
__device__ float g_kpe  [SQ*DROPE];
__device__ float g_ao   [SQ*HDV];
__device__ float g_wo   [DIM*HDV];

// ---------------------------------------------------------------------------
// helpers
// ---------------------------------------------------------------------------
__device__ __forceinline__ unsigned f2tf(float f) {
  unsigned u;
  asm("cvt.rna.tf32.f32 %0, %1;" : "=r"(u) : "f"(f));
  return u;
}
__device__ __forceinline__ float rtf(float f) { return __uint_as_float(f2tf(f)); }

__device__ __forceinline__ unsigned smem_u32(const void* p){
  unsigned a;
  asm("{ .reg .u64 t; cvta.to.shared.u64 t, %1; cvt.u32.u64 %0, t; }" : "=r"(a) : "l"(p));
  return a;
}
__device__ __forceinline__ void cp16(unsigned dst, const float* src){
  asm volatile("cp.async.cg.shared.global [%0], [%1], 16;" :: "r"(dst), "l"(src));
}
__device__ __forceinline__ void cp_commit(){ asm volatile("cp.async.commit_group;" ::: "memory"); }
__device__ __forceinline__ void cp_wait2(){ asm volatile("cp.async.wait_group 2;" ::: "memory"); }

__device__ __forceinline__ void mma_tf32(float* d, const unsigned* a, const unsigned* b) {
  asm volatile(
    "mma.sync.aligned.m16n8k8.row.col.f32.tf32.tf32.f32 "
    "{%0,%1,%2,%3},{%4,%5,%6,%7},{%8,%9},{%0,%1,%2,%3};"
    : "+f"(d[0]), "+f"(d[1]), "+f"(d[2]), "+f"(d[3])
    : "r"(a[0]), "r"(a[1]), "r"(a[2]), "r"(a[3]), "r"(b[0]), "r"(b[1]));
}

// elementwise tf32 rounding (float4 vectorized); n4 = n/4
__global__ void __launch_bounds__(256) round4_kernel(
    const float4* __restrict__ src, float4* __restrict__ dst, int n4) {
  int i = blockIdx.x * 256 + threadIdx.x;
  if (i < n4) {
    float4 v = src[i];
    dst[i] = make_float4(rtf(v.x), rtf(v.y), rtf(v.z), rtf(v.w));
  }
}

// ---------------------------------------------------------------------------
// TF32 tensor-core NT GEMM, cp.async 4-stage pipeline.
// C[M,N] = A[M,K] * B[N,K]^T, row-major, operands PRE-ROUNDED to tf32 values.
// CTA tile 128x128x16, 256 threads, warp tile 64x32 (m16n8k8).
// Requires M%128==0, N%128==0, K%16==0, K>=64.
// smem: 4 stages x (A 8KB + B 8KB) = 64KB dynamic. XOR swizzle:
//   word(row,k) = row*16 + ((k>>2) ^ ((row^(row>>2))&3))*4 + (k&3)
// ---------------------------------------------------------------------------
#define STAGES 4
#define AW 2048   // words per stage per operand (128 rows * 16 k)

__global__ void __launch_bounds__(256, 2) gemm_tf32_cp(
    const float* __restrict__ A, const float* __restrict__ B,
    float* __restrict__ C, int M, int N, int K) {
  extern __shared__ unsigned sm[];
  const int KT = K >> 4;
  const int bm = blockIdx.x * 128;
  const int bn = blockIdx.y * 128;
  const int tid  = threadIdx.x;
  const int lane = tid & 31;
  const int w    = tid >> 5;
  const int wm   = (w & 1) * 64;
  const int wn   = (w >> 1) * 32;
  const int g    = lane >> 2;
  const int tig  = lane & 3;

  // staging: thread -> 2 A chunks + 2 B chunks (16B each) per stage
  const int sr = tid >> 2;        // 0..63
  const int kc = tid & 3;         // chunk (4 k-values)
  const float* gA0 = A + (size_t)(bm + sr) * K + kc * 4;
  const float* gA1 = gA0 + (size_t)64 * K;
  const float* gB0 = B + (size_t)(bn + sr) * K + kc * 4;
  const float* gB1 = gB0 + (size_t)64 * K;
  const unsigned sb = smem_u32(sm);
  #define SWZ(r) (((r) ^ ((r) >> 2)) & 3)
  const unsigned dA0 = sb + 4u * ( sr      * 16 + ((kc ^ SWZ(sr))      << 2) );
  const unsigned dA1 = sb + 4u * ((sr + 64)* 16 + ((kc ^ SWZ(sr + 64)) << 2) );
  const unsigned dB0 = dA0 + 4u * STAGES * AW;
  const unsigned dB1 = dA1 + 4u * STAGES * AW;

  // fragment address precompute (word offsets; chunk xor applied inline)
  int aoff0[4], aoff1[4], asz0[4], asz1[4], boff[4], bsz[4];
#pragma unroll
  for (int mt = 0; mt < 4; mt++) {
    int r0 = wm + mt * 16 + g, r1 = r0 + 8;
    aoff0[mt] = r0 * 16 + tig; asz0[mt] = SWZ(r0);
    aoff1[mt] = r1 * 16 + tig; asz1[mt] = SWZ(r1);
  }
#pragma unroll
  for (int nt = 0; nt < 4; nt++) {
    int cn = wn + nt * 8 + g;
    boff[nt] = cn * 16 + tig; bsz[nt] = SWZ(cn);
  }

  float acc[4][4][4];
#pragma unroll
  for (int mt = 0; mt < 4; mt++)
#pragma unroll
    for (int nt = 0; nt < 4; nt++)
#pragma unroll
      for (int i = 0; i < 4; i++) acc[mt][nt][i] = 0.f;

  auto issue = [&](int s) {
    if (s < KT) {
      const unsigned so = ((unsigned)(s & 3) * AW) << 2;
      const size_t go = (size_t)s * 16;
      cp16(dA0 + so, gA0 + go);
      cp16(dA1 + so, gA1 + go);
      cp16(dB0 + so, gB0 + go);
      cp16(dB1 + so, gB1 + go);
    }
    cp_commit();
  };
  issue(0); issue(1); issue(2);

  for (int kt = 0; kt < KT; ++kt) {
    cp_wait2();
    __syncthreads();
    issue(kt + 3);
    const unsigned aB = (unsigned)(kt & 3) * AW;
    const unsigned bB = STAGES * AW + (unsigned)(kt & 3) * AW;
#pragma unroll
    for (int ks = 0; ks < 2; ++ks) {
      const int kc0 = ks << 1;
      unsigned af[4][4], bf[4][2];
#pragma unroll
      for (int mt = 0; mt < 4; mt++) {
        af[mt][0] = sm[aB + aoff0[mt] + (((kc0    ) ^ asz0[mt]) << 2)];
        af[mt][1] = sm[aB + aoff1[mt] + (((kc0    ) ^ asz1[mt]) << 2)];
        af[mt][2] = sm[aB + aoff0[mt] + (((kc0 + 1) ^ asz0[mt]) << 2)];
        af[mt][3] = sm[aB + aoff1[mt] + (((kc0 + 1) ^ asz1[mt]) << 2)];
      }
#pragma unroll
      for (int nt = 0; nt < 4; nt++) {
        bf[nt][0] = sm[bB + boff[nt] + (((kc0    ) ^ bsz[nt]) << 2)];
        bf[nt][1] = sm[bB + boff[nt] + (((kc0 + 1) ^ bsz[nt]) << 2)];
      }
#pragma unroll
      for (int mt = 0; mt < 4; mt++)
#pragma unroll
        for (int nt = 0; nt < 4; nt++)
          mma_tf32(acc[mt][nt], af[mt], bf[nt]);
    }
  }

  // epilogue
#pragma unroll
  for (int mt = 0; mt < 4; mt++) {
    const int row = bm + wm + mt * 16 + g;
#pragma unroll
    for (int nt = 0; nt < 4; nt++) {
      const int col = bn + wn + nt * 8 + 2 * tig;
      *(float2*)(C + (size_t)row * N + col)       = make_float2(acc[mt][nt][0], acc[mt][nt][1]);
      *(float2*)(C + (size_t)(row + 8) * N + col) = make_float2(acc[mt][nt][2], acc[mt][nt][3]);
    }
  }
}

// ---------------------------------------------------------------------------
// RMSNorm: out = x * rsqrt(mean(x^2)+eps) * w, rounded to tf32 for next GEMM.
// ---------------------------------------------------------------------------
__global__ void __launch_bounds__(256) rmsnorm_kernel(
    const float* __restrict__ in, const float* __restrict__ w,
    float* __restrict__ out, int n, int istride, int ostride) {
  const int row = blockIdx.x;
  const float* x = in + (size_t)row * istride;
  float s = 0.f;
  for (int i = threadIdx.x; i < n; i += 256) { float v = x[i]; s += v*v; }
  __shared__ float red[256];
  red[threadIdx.x] = s;
  __syncthreads();
  for (int off = 128; off > 0; off >>= 1) {
    if (threadIdx.x < off) red[threadIdx.x] += red[threadIdx.x + off];
    __syncthreads();
  }
  const float inv = rsqrtf(red[0] / (float)n + EPS);
  float* o = out + (size_t)row * ostride;
  for (int i = threadIdx.x; i < n; i += 256) o[i] = rtf(x[i] * inv * w[i]);
}

// ---------------------------------------------------------------------------
// RoPE on q_pe (in-place in g_q).
// ---------------------------------------------------------------------------
__global__ void rope_q_kernel(float* __restrict__ q,
                              const float* __restrict__ cosb,
                              const float* __restrict__ sinb) {
  int idx = blockIdx.x * blockDim.x + threadIdx.x;   // SQ*NH*32
  int d = idx & 31;
  int h = (idx >> 5) & (NH - 1);
  int s = idx >> 12;
  float* base = q + (size_t)s * HDQ + h * DQH + DNOPE;
  float x1 = base[d], x2 = base[d + 32];
  float c1 = cosb[s*DROPE + d],      s1 = sinb[s*DROPE + d];
  float c2 = cosb[s*DROPE + d + 32], s2 = sinb[s*DROPE + d + 32];
  base[d]      = x1*c1 - x2*s1;
  base[d + 32] = x2*c2 + x1*s2;
}

// RoPE on k_pe (from qkva cols [2048, 2112)) -> g_kpe[S, 64]
__global__ void rope_k_kernel(const float* __restrict__ qkva,
                              const float* __restrict__ cosb,
                              const float* __restrict__ sinb,
                              float* __restrict__ kpe) {
  int idx = blockIdx.x * blockDim.x + threadIdx.x;  // SQ*32
  int d = idx & 31;
  int s = idx >> 5;
  float x1 = qkva[(size_t)s*NCAT + (RQ+RKV) + d];
  float x2 = qkva[(size_t)s*NCAT + (RQ+RKV) + 32 + d];
  float c1 = cosb[s*DROPE + d],      s1 = sinb[s*DROPE + d];
  float c2 = cosb[s*DROPE + d + 32], s2 = sinb[s*DROPE + d + 32];
  kpe[s*DROPE + d]      = x1*c1 - x2*s1;
  kpe[s*DROPE + 32 + d] = x2*c2 + x1*s2;
}

// ---------------------------------------------------------------------------
// Flash attention (causal), one block per (head, 64-row q tile), 256 threads.
// Output rounded to tf32 (feeds the wo GEMM).
// ---------------------------------------------------------------------------
#define QK_STR 193
#define PS_STR 65
#define FLASH_SMEM ((2*64*QK_STR + 64*128 + 64*PS_STR) * 4)

__global__ void __launch_bounds__(256) flash_kernel(
    const float* __restrict__ q, const float* __restrict__ kv,
    const float* __restrict__ kpe, float* __restrict__ ao) {
  extern __shared__ float smf[];
  float* Qs = smf;                     // 64 x QK_STR
  float* Ks = Qs + 64*QK_STR;          // 64 x QK_STR
  float* Vs = Ks + 64*QK_STR;          // 64 x 128
  float* Ps = Vs + 64*128;             // 64 x PS_STR

  const int h  = blockIdx.x;
  const int q0 = blockIdx.y * 64;
  const int tid = threadIdx.x;
  const int r = tid >> 2;
  const int g = tid & 3;

  for (int idx = tid; idx < 64*DQH; idx += 256) {
    int row = idx / DQH, d = idx % DQH;
    Qs[row*QK_STR + d] = q[(size_t)(q0+row)*HDQ + h*DQH + d];
  }

  float m = -INFINITY, l = 0.f;
  float o[32];
#pragma unroll
  for (int c = 0; c < 32; c++) o[c] = 0.f;
  const float scale = rsqrtf((float)DQH);

  const int nkt = blockIdx.y + 1;
  for (int kt = 0; kt < nkt; kt++) {
    const int k0 = kt * 64;
    __syncthreads();
    for (int idx = tid; idx < 64*DQH; idx += 256) {
      int row = idx / DQH, d = idx % DQH;
      Ks[row*QK_STR + d] = (d < DNOPE)
          ? kv[(size_t)(k0+row)*HKV + h*(DNOPE+DVAL) + d]
          : kpe[(k0+row)*DROPE + (d - DNOPE)];
    }
    for (int idx = tid; idx < 64*128; idx += 256) {
      int row = idx >> 7, d = idx & 127;
      Vs[idx] = kv[(size_t)(k0+row)*HKV + h*(DNOPE+DVAL) + DNOPE + d];
    }
    __syncthreads();

    float sc[16];
#pragma unroll
    for (int j = 0; j < 16; j++) sc[j] = 0.f;
    const float* qr = Qs + r*QK_STR;
    for (int d0 = 0; d0 < DQH; d0 += 8) {
      float qd[8];
#pragma unroll
      for (int dd = 0; dd < 8; dd++) qd[dd] = qr[d0+dd];
#pragma unroll
      for (int j = 0; j < 16; j++) {
        const float* kr = Ks + (g*16+j)*QK_STR + d0;
#pragma unroll
        for (int dd = 0; dd < 8; dd++) sc[j] += qd[dd]*kr[dd];
      }
    }
#pragma unroll
    for (int j = 0; j < 16; j++) {
      int c = g*16 + j;
      sc[j] = (k0 + c <= q0 + r) ? sc[j]*scale : -INFINITY;
    }

    float mloc = -INFINITY;
#pragma unroll
    for (int j = 0; j < 16; j++) mloc = fmaxf(mloc, sc[j]);
    mloc = fmaxf(mloc, __shfl_xor_sync(0xffffffffu, mloc, 1));
    mloc = fmaxf(mloc, __shfl_xor_sync(0xffffffffu, mloc, 2));
    float mnew = fmaxf(m, mloc);
    float alpha = expf(m - mnew);
    float lloc = 0.f;
#pragma unroll
    for (int j = 0; j < 16; j++) {
      float p = expf(sc[j] - mnew);
      lloc += p;
      Ps[r*PS_STR + g*16 + j] = p;
    }
    lloc += __shfl_xor_sync(0xffffffffu, lloc, 1);
    lloc += __shfl_xor_sync(0xffffffffu, lloc, 2);
    l = l * alpha + lloc;
    m = mnew;
#pragma unroll
    for (int c = 0; c < 32; c++) o[c] *= alpha;

    __syncwarp();
    const float* psr = Ps + r*PS_STR;
    for (int j = 0; j < 64; j++) {
      float pj = psr[j];
      const float* vr = Vs + j*128 + g;
#pragma unroll
      for (int c = 0; c < 32; c++) o[c] += pj * vr[4*c];
    }
  }

  const float invl = 1.f / l;
#pragma unroll
  for (int c = 0; c < 32; c++)
    ao[(size_t)(q0+r)*HDV + h*DVAL + g + 4*c] = rtf(o[c] * invl);
}

// ---------------------------------------------------------------------------
extern "C" void kernel_launch(void* const* d_in, const int* in_sizes, int n_in,
                              void* d_out, int out_size) {
  const float* hidden  = (const float*)d_in[0];
  const float* cosb    = (const float*)d_in[1];
  const float* sinb    = (const float*)d_in[2];
  const float* wq_a    = (const float*)d_in[3];
  const float* q_ln_w  = (const float*)d_in[4];
  const float* wq_b    = (const float*)d_in[5];
  const float* wkv_a   = (const float*)d_in[6];
  const float* kv_ln_w = (const float*)d_in[7];
  const float* wkv_b   = (const float*)d_in[8];
  const float* wo      = (const float*)d_in[9];
  float* out = (float*)d_out;

  float *hid, *wqkva, *qkva, *qan, *wqb, *q, *kvn, *wkvb, *kv, *kpe, *ao, *woR;
  cudaGetSymbolAddress((void**)&hid,   g_hid);
  cudaGetSymbolAddress((void**)&wqkva, g_wqkva);
  cudaGetSymbolAddress((void**)&qkva,  g_qkva);
  cudaGetSymbolAddress((void**)&qan,   g_qan);
  cudaGetSymbolAddress((void**)&wqb,   g_wqb);
  cudaGetSymbolAddress((void**)&q,     g_q);
  cudaGetSymbolAddress((void**)&kvn,   g_kvn);
  cudaGetSymbolAddress((void**)&wkvb,  g_wkvb);
  cudaGetSymbolAddress((void**)&kv,    g_kv);
  cudaGetSymbolAddress((void**)&kpe,   g_kpe);
  cudaGetSymbolAddress((void**)&ao,    g_ao);
  cudaGetSymbolAddress((void**)&woR,   g_wo);

  cudaFuncSetAttribute(gemm_tf32_cp, cudaFuncAttributeMaxDynamicSharedMemorySize,
                       STAGES * 2 * AW * 4);
  cudaFuncSetAttribute(flash_kernel, cudaFuncAttributeMaxDynamicSharedMemorySize, FLASH_SMEM);

  // pre-round operands to tf32 values (rna), re-layout wq_a||wkv_a into padded concat
  auto rnd = [](const float* s, float* d, int n) {
    round4_kernel<<<(n/4 + 255)/256, 256>>>((const float4*)s, (float4*)d, n/4);
  };
  rnd(hidden, hid,   SQ*DIM);
  rnd(wq_a,   wqkva, RQ*DIM);
  rnd(wkv_a,  wqkva + (size_t)RQ*DIM, (RKV+DROPE)*DIM);   // rows 2112..2175 stay 0
  rnd(wq_b,   wqb,   HDQ*RQ);
  rnd(wkv_b,  wkvb,  HKV*RKV);
  rnd(wo,     woR,   DIM*HDV);

  const int GSM = STAGES * 2 * AW * 4;

  // fused q_a + kv_a projection: qkva[1024, 2176]
  gemm_tf32_cp<<<dim3(SQ/128, NCAT/128), 256, GSM>>>(hid, wqkva, qkva, SQ, NCAT, DIM);

  // q path
  rmsnorm_kernel<<<SQ, 256>>>(qkva, q_ln_w, qan, RQ, NCAT, RQ);
  gemm_tf32_cp<<<dim3(SQ/128, HDQ/128), 256, GSM>>>(qan, wqb, q, SQ, HDQ, RQ);

  // kv path
  rmsnorm_kernel<<<SQ, 256>>>(qkva + RQ, kv_ln_w, kvn, RKV, NCAT, RKV);
  gemm_tf32_cp<<<dim3(SQ/128, HKV/128), 256, GSM>>>(kvn, wkvb, kv, SQ, HKV, RKV);

  // RoPE
  rope_q_kernel<<<(SQ*NH*32)/256, 256>>>(q, cosb, sinb);
  rope_k_kernel<<<(SQ*32)/256, 256>>>(qkva, cosb, sinb, kpe);

  // causal flash attention (rounds its output)
  flash_kernel<<<dim3(NH, SQ/64), 256, FLASH_SMEM>>>(q, kv, kpe, ao);

  // output projection
  gemm_tf32_cp<<<dim3(SQ/128, DIM/128), 256, GSM>>>(ao, woR, out, SQ, DIM, HDV);
}